// round 5
// baseline (speedup 1.0000x reference)
#include <cuda_runtime.h>
#include <cstdint>
#include <cstddef>
#include <cub/cub.cuh>

// ---------------------------------------------------------------------------
// Problem constants
// ---------------------------------------------------------------------------
#define IMG_W 512
#define IMG_H 512
#define BATCH 32
#define NPI   (IMG_W * IMG_H)     // 262144 pixels per image
#define NTOT  (BATCH * NPI)       // 8388608 total

#define ALPHA 0.3
#define BETA  0.3
#define GAMMA 0.2
#define DELTA 0.2
#define EPS_D 1e-7

// pass1 tiling
#define P1_ROWS    8
#define P1_BPI     (IMG_H / P1_ROWS)          // 64 blocks per image
#define P1_BLOCKS  (BATCH * P1_BPI)           // 2048

// lovasz tiling
#define TILE          8192
#define NTILES        (NTOT / TILE)           // 1024
#define TILES_PER_IMG (NPI / TILE)            // 32

// ---------------------------------------------------------------------------
// Static device scratch (no allocations allowed)
// ---------------------------------------------------------------------------
__device__ __align__(16) uint32_t g_keys_a[NTOT];
__device__ __align__(16) uint32_t g_keys_b[NTOT];
__device__ __align__(16) unsigned char g_temp[64u * 1024u * 1024u];

__device__ float g_bce_part[P1_BLOCKS];
__device__ float g_bnd_part[P1_BLOCKS];
__device__ float g_pt_part [P1_BLOCKS];
__device__ float g_ppt_part[P1_BLOCKS];

__device__ int   g_tileCnt[NTILES];
__device__ int   g_tileOff[NTILES];
__device__ int   g_G[BATCH];
__device__ float g_lov_part[NTILES];

// ---------------------------------------------------------------------------
// Pass 1: fused BCE + dice partials + boundary-weighted BCE + sort-key build
//
// Key layout (ascending sort == per-image descending error):
//   bits [31:27] image id, bits [26:1] 26-bit monotone descending-error code,
//   bit 0 = y (label). Ties in error provably do not affect the lovasz sum.
// ---------------------------------------------------------------------------
__global__ __launch_bounds__(128) void pass1_kernel(
    const float* __restrict__ logits, const float* __restrict__ targets)
{
    // shared target rows with 4-float left pad (data at [4 + x]), zero halos
    __shared__ float ts[3][IMG_W + 8];

    const int tid = threadIdx.x;
    const int blk = blockIdx.x;
    const int img = blk >> 6;                   // / P1_BPI
    const int y0  = (blk & 63) * P1_ROWS;
    const int x0  = tid * 4;

    const float* tg = targets + (size_t)img * NPI;
    const float* lg = logits  + (size_t)img * NPI;
    uint32_t*  kout = g_keys_a + (size_t)img * NPI;

    if (tid < 3) { ts[tid][3] = 0.f; ts[tid][4 + IMG_W] = 0.f; }

    // preload rows y0-1 (slot 0) and y0 (slot 1)
    {
        float4 v = make_float4(0.f, 0.f, 0.f, 0.f);
        if (y0 - 1 >= 0)
            v = *reinterpret_cast<const float4*>(tg + (size_t)(y0 - 1) * IMG_W + x0);
        *reinterpret_cast<float4*>(&ts[0][4 + x0]) = v;
        v = *reinterpret_cast<const float4*>(tg + (size_t)y0 * IMG_W + x0);
        *reinterpret_cast<float4*>(&ts[1][4 + x0]) = v;
    }

    float s_bce = 0.f, s_bnd = 0.f, s_pt = 0.f, s_ppt = 0.f;

    for (int r = 0; r < P1_ROWS; r++) {
        const int y  = y0 + r;
        const int sp = r % 3, sc = (r + 1) % 3, sn = (r + 2) % 3;

        // load next target row into slot sn
        float4 v = make_float4(0.f, 0.f, 0.f, 0.f);
        if (y + 1 < IMG_H)
            v = *reinterpret_cast<const float4*>(tg + (size_t)(y + 1) * IMG_W + x0);
        __syncthreads();                       // prior readers of slot sn done
        *reinterpret_cast<float4*>(&ts[sn][4 + x0]) = v;
        __syncthreads();                       // all three rows visible

        const float4 x4 = *reinterpret_cast<const float4*>(lg + (size_t)y * IMG_W + x0);
        const float xs[4] = {x4.x, x4.y, x4.z, x4.w};
        uint32_t keys[4];

        #pragma unroll
        for (int j = 0; j < 4; j++) {
            const int xx = x0 + j;
            const float t = ts[sc][4 + xx];
            const float ns =
                ts[sp][3 + xx] + ts[sp][4 + xx] + ts[sp][5 + xx] +
                ts[sc][3 + xx] + ts[sc][4 + xx] + ts[sc][5 + xx] +
                ts[sn][3 + xx] + ts[sn][4 + xx] + ts[sn][5 + xx];

            const float x  = xs[j];
            const float ax = fabsf(x);
            const float bce = fmaxf(x, 0.f) - x * t + log1pf(__expf(-ax));
            const float wgt = (ns >= 0.5f && ns <= 8.5f) ? 3.0f : 1.0f;
            const float p   = 1.0f / (1.0f + __expf(-x));

            s_bce += bce;
            s_bnd += bce * wgt;
            s_pt  += p * t;
            s_ppt += p + t;

            const float e  = 1.0f - x * (2.0f * t - 1.0f);
            const uint32_t u    = __float_as_uint(e);
            const uint32_t asc  = (u & 0x80000000u) ? ~u : (u | 0x80000000u);
            const uint32_t desc = ~asc;                    // ascending == descending e
            const uint32_t yb   = (t > 0.5f) ? 1u : 0u;
            keys[j] = ((uint32_t)img << 27) | ((desc >> 6) << 1) | yb;
        }
        *reinterpret_cast<uint4*>(kout + (size_t)y * IMG_W + x0) =
            make_uint4(keys[0], keys[1], keys[2], keys[3]);
    }

    // block reduce the 4 partial sums (4 warps of 32)
    const int lane = tid & 31, warp = tid >> 5;
    #pragma unroll
    for (int o = 16; o; o >>= 1) {
        s_bce += __shfl_down_sync(0xffffffffu, s_bce, o);
        s_bnd += __shfl_down_sync(0xffffffffu, s_bnd, o);
        s_pt  += __shfl_down_sync(0xffffffffu, s_pt,  o);
        s_ppt += __shfl_down_sync(0xffffffffu, s_ppt, o);
    }
    __shared__ float4 wred[4];
    if (lane == 0) wred[warp] = make_float4(s_bce, s_bnd, s_pt, s_ppt);
    __syncthreads();
    if (tid == 0) {
        float4 s = wred[0];
        for (int w = 1; w < 4; w++) {
            s.x += wred[w].x; s.y += wred[w].y; s.z += wred[w].z; s.w += wred[w].w;
        }
        g_bce_part[blk] = s.x;
        g_bnd_part[blk] = s.y;
        g_pt_part [blk] = s.z;
        g_ppt_part[blk] = s.w;
    }
}

// ---------------------------------------------------------------------------
// Count y-bits per tile of the sorted key array
// ---------------------------------------------------------------------------
__global__ __launch_bounds__(256) void count_kernel()
{
    const int t = blockIdx.x, tid = threadIdx.x;
    const uint4* base = reinterpret_cast<const uint4*>(g_keys_b) + (size_t)t * (TILE / 4);
    int c = 0;
    #pragma unroll
    for (int i = 0; i < TILE / 1024; i++) {
        uint4 v = base[i * 256 + tid];
        c += (int)(v.x & 1u) + (int)(v.y & 1u) + (int)(v.z & 1u) + (int)(v.w & 1u);
    }
    #pragma unroll
    for (int o = 16; o; o >>= 1) c += __shfl_down_sync(0xffffffffu, c, o);
    __shared__ int wsum[8];
    if ((tid & 31) == 0) wsum[tid >> 5] = c;
    __syncthreads();
    if (tid == 0) {
        int s = 0;
        #pragma unroll
        for (int w = 0; w < 8; w++) s += wsum[w];
        g_tileCnt[t] = s;
    }
}

// ---------------------------------------------------------------------------
// Per-image exclusive scan of tile counts (+ total positives G per image)
// ---------------------------------------------------------------------------
__global__ __launch_bounds__(1024) void scan_kernel()
{
    const int tid  = threadIdx.x;
    const int im   = tid >> 5;       // 32 images == 32 warps
    const int lane = tid & 31;       // 32 tiles per image == 32 lanes
    const int v    = g_tileCnt[im * TILES_PER_IMG + lane];
    int inc = v;
    #pragma unroll
    for (int o = 1; o < 32; o <<= 1) {
        int n = __shfl_up_sync(0xffffffffu, inc, o);
        if (lane >= o) inc += n;
    }
    g_tileOff[im * TILES_PER_IMG + lane] = inc - v;
    if (lane == 31) g_G[im] = inc;
}

// ---------------------------------------------------------------------------
// Lovasz: segmented scan over sorted keys.
//   c_i = inclusive prefix count of positives (ballot/popc within chunk),
//   U_i = G + i - c_i,
//   g_i = 1/U_i          (y=1)
//       = (G-c_i)/(U_i(U_i-1))  (y=0)
//   term = relu(e_i) * g_i
// ---------------------------------------------------------------------------
__global__ __launch_bounds__(256) void lovasz_kernel()
{
    const int t    = blockIdx.x, tid = threadIdx.x;
    const int warp = tid >> 5, lane = tid & 31;
    const int im   = t >> 5;                       // / TILES_PER_IMG
    const int ibase = (t & 31) * TILE;             // element base within image
    const uint32_t* keys = g_keys_b + (size_t)t * TILE;

    const int G = g_G[im];
    int c_run   = g_tileOff[t];

    __shared__ int wcnt[8];
    float lsum = 0.f;

    for (int ch = 0; ch < TILE / 256; ch++) {
        const uint32_t key = keys[ch * 256 + tid];
        const int yb = (int)(key & 1u);

        // decode quantized error
        const uint32_t e26  = (key >> 1) & 0x03FFFFFFu;
        const uint32_t desc = (e26 << 6) | 32u;
        const uint32_t asc  = ~desc;
        const uint32_t ub   = (asc & 0x80000000u) ? (asc ^ 0x80000000u) : ~asc;
        const float e = __uint_as_float(ub);

        const unsigned bal = __ballot_sync(0xffffffffu, yb);
        const int within = __popc(bal & (0xffffffffu >> (31 - lane)));  // inclusive
        if (lane == 0) wcnt[warp] = __popc(bal);
        __syncthreads();

        int off = 0, tot = 0;
        #pragma unroll
        for (int w = 0; w < 8; w++) {
            const int wv = wcnt[w];
            tot += wv;
            if (w < warp) off += wv;
        }

        const int c = c_run + off + within;                // inclusive count
        const int i = ibase + ch * 256 + tid + 1;          // 1-indexed rank
        const int U = G + i - c;

        float g;
        if (yb)            g = 1.0f / (float)U;
        else if (U > 1)    g = (float)(G - c) / ((float)U * (float)(U - 1));
        else               g = (i == 1) ? 1.0f : 0.0f;     // degenerate G==0 case

        lsum += fmaxf(e, 0.f) * g;
        c_run += tot;
        __syncthreads();
    }

    #pragma unroll
    for (int o = 16; o; o >>= 1) lsum += __shfl_down_sync(0xffffffffu, lsum, o);
    __shared__ float wred[8];
    if (lane == 0) wred[warp] = lsum;
    __syncthreads();
    if (tid == 0) {
        float s = 0.f;
        #pragma unroll
        for (int w = 0; w < 8; w++) s += wred[w];
        g_lov_part[t] = s;
    }
}

// ---------------------------------------------------------------------------
// Deterministic final combine (fixed-order double-precision sums)
// ---------------------------------------------------------------------------
__global__ __launch_bounds__(256) void final_kernel(float* __restrict__ out)
{
    const int tid = threadIdx.x;
    __shared__ double red[256];

    // BCE sum
    double a = 0.0;
    for (int i = tid; i < P1_BLOCKS; i += 256) a += (double)g_bce_part[i];
    red[tid] = a; __syncthreads();
    for (int o = 128; o; o >>= 1) { if (tid < o) red[tid] += red[tid + o]; __syncthreads(); }
    const double bce_sum = red[0]; __syncthreads();

    // Boundary sum
    a = 0.0;
    for (int i = tid; i < P1_BLOCKS; i += 256) a += (double)g_bnd_part[i];
    red[tid] = a; __syncthreads();
    for (int o = 128; o; o >>= 1) { if (tid < o) red[tid] += red[tid + o]; __syncthreads(); }
    const double bnd_sum = red[0]; __syncthreads();

    // Dice ratios per image
    a = 0.0;
    if (tid < BATCH) {
        double pt = 0.0, ppt = 0.0;
        for (int b = tid * P1_BPI; b < (tid + 1) * P1_BPI; b++) {
            pt  += (double)g_pt_part [b];
            ppt += (double)g_ppt_part[b];
        }
        a = 2.0 * pt / (ppt + EPS_D);
    }
    red[tid] = a; __syncthreads();
    for (int o = 128; o; o >>= 1) { if (tid < o) red[tid] += red[tid + o]; __syncthreads(); }
    const double dice_sum = red[0]; __syncthreads();

    // Lovasz per image
    a = 0.0;
    if (tid < BATCH) {
        double lv = 0.0;
        for (int tt = tid * TILES_PER_IMG; tt < (tid + 1) * TILES_PER_IMG; tt++)
            lv += (double)g_lov_part[tt];
        a = lv;
    }
    red[tid] = a; __syncthreads();
    for (int o = 128; o; o >>= 1) { if (tid < o) red[tid] += red[tid + o]; __syncthreads(); }
    const double lov_sum = red[0];

    if (tid == 0) {
        const double invN = 1.0 / (double)NTOT;
        const double loss = ALPHA * (bce_sum * invN)
                          + BETA  * (1.0 - dice_sum / (double)BATCH)
                          + GAMMA * (bnd_sum * invN)
                          + DELTA * (lov_sum / (double)BATCH);
        out[0] = (float)loss;
    }
}

// ---------------------------------------------------------------------------
// Launch
// ---------------------------------------------------------------------------
extern "C" void kernel_launch(void* const* d_in, const int* in_sizes, int n_in,
                              void* d_out, int out_size)
{
    const float* logits  = (const float*)d_in[0];
    const float* targets = (const float*)d_in[1];

    void *keys_a = nullptr, *keys_b = nullptr, *tmp = nullptr;
    cudaGetSymbolAddress(&keys_a, g_keys_a);
    cudaGetSymbolAddress(&keys_b, g_keys_b);
    cudaGetSymbolAddress(&tmp,    g_temp);

    pass1_kernel<<<P1_BLOCKS, 128>>>(logits, targets);

    size_t tb = 0;
    cub::DeviceRadixSort::SortKeys(nullptr, tb,
                                   (const uint32_t*)keys_a, (uint32_t*)keys_b,
                                   (int)NTOT, 0, 32);
    if (tb > sizeof(g_temp)) tb = sizeof(g_temp);   // defensive; never expected
    cub::DeviceRadixSort::SortKeys(tmp, tb,
                                   (const uint32_t*)keys_a, (uint32_t*)keys_b,
                                   (int)NTOT, 0, 32);

    count_kernel <<<NTILES, 256>>>();
    scan_kernel  <<<1, 1024>>>();
    lovasz_kernel<<<NTILES, 256>>>();
    final_kernel <<<1, 256>>>((float*)d_out);
}

// round 8
// speedup vs baseline: 2.7168x; 2.7168x over previous
#include <cuda_runtime.h>
#include <cstdint>
#include <cstddef>

// ---------------------------------------------------------------------------
// Problem constants
// ---------------------------------------------------------------------------
#define IMG_W 512
#define IMG_H 512
#define BATCH 32
#define NPI   (IMG_W * IMG_H)     // 262144 pixels per image
#define NTOT  (BATCH * NPI)       // 8388608 total

#define ALPHA 0.3
#define BETA  0.3
#define GAMMA 0.2
#define DELTA 0.2
#define EPS_D 1e-7

// pass1 tiling
#define P1_ROWS    8
#define P1_BPI     (IMG_H / P1_ROWS)          // 64 blocks per image
#define P1_BLOCKS  (BATCH * P1_BPI)           // 2048

// histogram / lovasz tiling
#define NB        65536                       // error buckets per image
#define HSCALE    8192.0f                     // NB / 8.0 (e range [0,8])
#define HSTEP     1.220703125e-4f             // 8.0 / NB
#define HTILE     2048                        // buckets per block
#define HT_PER_IMG (NB / HTILE)               // 32
#define NHTILES   (BATCH * HT_PER_IMG)        // 1024

// ---------------------------------------------------------------------------
// Static device scratch (no allocations allowed)
// ---------------------------------------------------------------------------
// per (image, reversed-bucket): positives in high 16 bits, negatives in low 16
__device__ __align__(16) uint32_t g_hist[(size_t)BATCH * NB];   // 8 MB

__device__ float g_bce_part[P1_BLOCKS];
__device__ float g_bnd_part[P1_BLOCKS];
__device__ float g_pt_part [P1_BLOCKS];
__device__ float g_ppt_part[P1_BLOCKS];
__device__ int   g_cnt_part[P1_BLOCKS];       // positives per pass1 block

__device__ int   g_tpos[NHTILES];             // positives per hist tile
__device__ int   g_ttot[NHTILES];             // total (e>0) per hist tile
__device__ int   g_cOff[NHTILES];             // exclusive positive prefix
__device__ int   g_iOff[NHTILES];             // exclusive total prefix
__device__ int   g_G[BATCH];                  // total positives per image
__device__ float g_lov_part[NHTILES];

// ---------------------------------------------------------------------------
// Zero the histogram (must precede pass1 on every replay)
// ---------------------------------------------------------------------------
__global__ __launch_bounds__(256) void zero_hist_kernel()
{
    const size_t i = (size_t)blockIdx.x * 256 + threadIdx.x;
    reinterpret_cast<uint4*>(g_hist)[i] = make_uint4(0u, 0u, 0u, 0u);
}

// ---------------------------------------------------------------------------
// Pass 1: fused BCE + dice partials + boundary-weighted BCE + error histogram
// ---------------------------------------------------------------------------
__global__ __launch_bounds__(128) void pass1_kernel(
    const float* __restrict__ logits, const float* __restrict__ targets)
{
    __shared__ float ts[3][IMG_W + 8];        // 3 target rows, 4-float pads

    const int tid = threadIdx.x;
    const int blk = blockIdx.x;
    const int img = blk >> 6;                 // / P1_BPI
    const int y0  = (blk & 63) * P1_ROWS;
    const int x0  = tid * 4;

    const float* tg = targets + (size_t)img * NPI;
    const float* lg = logits  + (size_t)img * NPI;
    uint32_t*  hist = g_hist  + (size_t)img * NB;

    if (tid < 3) { ts[tid][3] = 0.f; ts[tid][4 + IMG_W] = 0.f; }

    {
        float4 v = make_float4(0.f, 0.f, 0.f, 0.f);
        if (y0 - 1 >= 0)
            v = *reinterpret_cast<const float4*>(tg + (size_t)(y0 - 1) * IMG_W + x0);
        *reinterpret_cast<float4*>(&ts[0][4 + x0]) = v;
        v = *reinterpret_cast<const float4*>(tg + (size_t)y0 * IMG_W + x0);
        *reinterpret_cast<float4*>(&ts[1][4 + x0]) = v;
    }

    float s_bce = 0.f, s_bnd = 0.f, s_pt = 0.f, s_ppt = 0.f;
    int   s_cnt = 0;

    for (int r = 0; r < P1_ROWS; r++) {
        const int y  = y0 + r;
        const int sp = r % 3, sc = (r + 1) % 3, sn = (r + 2) % 3;

        float4 v = make_float4(0.f, 0.f, 0.f, 0.f);
        if (y + 1 < IMG_H)
            v = *reinterpret_cast<const float4*>(tg + (size_t)(y + 1) * IMG_W + x0);
        __syncthreads();
        *reinterpret_cast<float4*>(&ts[sn][4 + x0]) = v;
        __syncthreads();

        const float4 x4 = *reinterpret_cast<const float4*>(lg + (size_t)y * IMG_W + x0);
        const float xs[4] = {x4.x, x4.y, x4.z, x4.w};

        #pragma unroll
        for (int j = 0; j < 4; j++) {
            const int xx = x0 + j;
            const float t = ts[sc][4 + xx];
            const float ns =
                ts[sp][3 + xx] + ts[sp][4 + xx] + ts[sp][5 + xx] +
                ts[sc][3 + xx] + ts[sc][4 + xx] + ts[sc][5 + xx] +
                ts[sn][3 + xx] + ts[sn][4 + xx] + ts[sn][5 + xx];

            const float x  = xs[j];
            const float ax = fabsf(x);
            const float bce = fmaxf(x, 0.f) - x * t + log1pf(__expf(-ax));
            const float wgt = (ns >= 0.5f && ns <= 8.5f) ? 3.0f : 1.0f;
            const float p   = 1.0f / (1.0f + __expf(-x));
            const int   yb  = (t > 0.5f) ? 1 : 0;

            s_bce += bce;
            s_bnd += bce * wgt;
            s_pt  += p * t;
            s_ppt += p + t;
            s_cnt += yb;

            // error histogram (linear buckets over (0, 8], reversed index:
            // ascending rb == descending e). e <= 0 contributes nothing and
            // sorts after everything relevant -> skip entirely.
            const float e = 1.0f - x * (2.0f * t - 1.0f);
            if (e > 0.0f) {
                int bkt = (int)(e * HSCALE);
                if (bkt > NB - 1) bkt = NB - 1;
                const int rb = (NB - 1) - bkt;
                atomicAdd(&hist[rb], yb ? 0x10000u : 1u);
            }
        }
    }

    // block reduce partials (4 warps)
    const int lane = tid & 31, warp = tid >> 5;
    #pragma unroll
    for (int o = 16; o; o >>= 1) {
        s_bce += __shfl_down_sync(0xffffffffu, s_bce, o);
        s_bnd += __shfl_down_sync(0xffffffffu, s_bnd, o);
        s_pt  += __shfl_down_sync(0xffffffffu, s_pt,  o);
        s_ppt += __shfl_down_sync(0xffffffffu, s_ppt, o);
        s_cnt += __shfl_down_sync(0xffffffffu, s_cnt, o);
    }
    __shared__ float4 wred[4];
    __shared__ int    wcnt[4];
    if (lane == 0) { wred[warp] = make_float4(s_bce, s_bnd, s_pt, s_ppt); wcnt[warp] = s_cnt; }
    __syncthreads();
    if (tid == 0) {
        float4 s = wred[0];
        int    c = wcnt[0];
        for (int w = 1; w < 4; w++) {
            s.x += wred[w].x; s.y += wred[w].y; s.z += wred[w].z; s.w += wred[w].w;
            c += wcnt[w];
        }
        g_bce_part[blk] = s.x;
        g_bnd_part[blk] = s.y;
        g_pt_part [blk] = s.z;
        g_ppt_part[blk] = s.w;
        g_cnt_part[blk] = c;
    }
}

// ---------------------------------------------------------------------------
// Per-tile (pos, tot) sums of the histogram
// ---------------------------------------------------------------------------
__global__ __launch_bounds__(256) void tilecount_kernel()
{
    const int t = blockIdx.x, tid = threadIdx.x;
    const int im = t >> 5;
    const uint32_t* h = g_hist + (size_t)im * NB + (size_t)(t & 31) * HTILE;

    const uint4 a = reinterpret_cast<const uint4*>(h)[tid * 2 + 0];
    const uint4 b = reinterpret_cast<const uint4*>(h)[tid * 2 + 1];
    const uint32_t v[8] = {a.x, a.y, a.z, a.w, b.x, b.y, b.z, b.w};

    int tp = 0, tt = 0;
    #pragma unroll
    for (int j = 0; j < 8; j++) {
        const int p = (int)(v[j] >> 16), n = (int)(v[j] & 0xffffu);
        tp += p; tt += p + n;
    }
    #pragma unroll
    for (int o = 16; o; o >>= 1) {
        tp += __shfl_down_sync(0xffffffffu, tp, o);
        tt += __shfl_down_sync(0xffffffffu, tt, o);
    }
    __shared__ int wp[8], wt[8];
    const int lane = tid & 31, warp = tid >> 5;
    if (lane == 0) { wp[warp] = tp; wt[warp] = tt; }
    __syncthreads();
    if (tid == 0) {
        int sp = 0, st = 0;
        #pragma unroll
        for (int w = 0; w < 8; w++) { sp += wp[w]; st += wt[w]; }
        g_tpos[t] = sp;
        g_ttot[t] = st;
    }
}

// ---------------------------------------------------------------------------
// Per-image exclusive scan of tile counts + total positives G per image
// (32 images == 32 warps; 32 tiles per image == 32 lanes)
// ---------------------------------------------------------------------------
__global__ __launch_bounds__(1024) void scan_kernel()
{
    const int tid  = threadIdx.x;
    const int im   = tid >> 5;
    const int lane = tid & 31;

    const int vp = g_tpos[im * HT_PER_IMG + lane];
    const int vt = g_ttot[im * HT_PER_IMG + lane];
    int ip = vp, it = vt;
    #pragma unroll
    for (int o = 1; o < 32; o <<= 1) {
        const int np = __shfl_up_sync(0xffffffffu, ip, o);
        const int nt = __shfl_up_sync(0xffffffffu, it, o);
        if (lane >= o) { ip += np; it += nt; }
    }
    g_cOff[im * HT_PER_IMG + lane] = ip - vp;
    g_iOff[im * HT_PER_IMG + lane] = it - vt;

    // G = total positives over the whole image (includes e<=0 elements)
    int c = g_cnt_part[im * 64 + lane] + g_cnt_part[im * 64 + 32 + lane];
    #pragma unroll
    for (int o = 16; o; o >>= 1) c += __shfl_down_sync(0xffffffffu, c, o);
    if (lane == 0) g_G[im] = c;
}

// ---------------------------------------------------------------------------
// Lovasz via closed-form per-bucket contributions.
// Positives-first within a bucket (tie order is provably irrelevant):
//   positives run : U = G + i0 - c0 constant  -> e * n1 / U
//   negatives run : telescoping               -> e * (G-c) * n0 / (a*(a+n0)),
//                   a = G + i0 + n1 - c,  c = c0 + n1
// ---------------------------------------------------------------------------
__global__ __launch_bounds__(256) void hlov_kernel()
{
    const int t = blockIdx.x, tid = threadIdx.x;
    const int lane = tid & 31, warp = tid >> 5;
    const int im = t >> 5;
    const uint32_t* h = g_hist + (size_t)im * NB + (size_t)(t & 31) * HTILE;

    const uint4 a4 = reinterpret_cast<const uint4*>(h)[tid * 2 + 0];
    const uint4 b4 = reinterpret_cast<const uint4*>(h)[tid * 2 + 1];
    const uint32_t v[8] = {a4.x, a4.y, a4.z, a4.w, b4.x, b4.y, b4.z, b4.w};

    // per-thread (tot<<32 | pos) totals, then block exclusive scan
    int tp = 0, tt = 0;
    #pragma unroll
    for (int j = 0; j < 8; j++) {
        const int p = (int)(v[j] >> 16), n = (int)(v[j] & 0xffffu);
        tp += p; tt += p + n;
    }
    unsigned long long pk  = ((unsigned long long)(unsigned)tt << 32) | (unsigned)tp;
    unsigned long long inc = pk;
    #pragma unroll
    for (int o = 1; o < 32; o <<= 1) {
        const unsigned long long nv = __shfl_up_sync(0xffffffffu, inc, o);
        if (lane >= o) inc += nv;
    }
    __shared__ unsigned long long wtot[8];
    if (lane == 31) wtot[warp] = inc;
    __syncthreads();
    unsigned long long woff = 0;
    for (int w = 0; w < warp; w++) woff += wtot[w];
    const unsigned long long excl = woff + inc - pk;

    const int G  = g_G[im];
    int i0 = g_iOff[t] + (int)(excl >> 32);
    int c0 = g_cOff[t] + (int)(excl & 0xffffffffu);

    const int rb0 = (t & 31) * HTILE + tid * 8;
    float acc = 0.f;

    #pragma unroll
    for (int j = 0; j < 8; j++) {
        const int n1 = (int)(v[j] >> 16), n0 = (int)(v[j] & 0xffffu);
        const int n = n1 + n0;
        if (n) {
            const int   b = (NB - 1) - (rb0 + j);
            const float e = ((float)b + 0.5f) * HSTEP;

            if (G == 0 && i0 == 0) acc += e;        // degenerate all-negative image
            if (n1) acc += e * (float)n1 / (float)(G + i0 - c0);
            const int c  = c0 + n1;
            const int Gc = G - c;
            if (n0 && Gc > 0) {
                const float aU = (float)(G + i0 + n1 - c);
                acc += e * (float)Gc * (float)n0 / (aU * (aU + (float)n0));
            }
            i0 += n; c0 += n1;
        }
    }

    #pragma unroll
    for (int o = 16; o; o >>= 1) acc += __shfl_down_sync(0xffffffffu, acc, o);
    __shared__ float wred[8];
    if (lane == 0) wred[warp] = acc;
    __syncthreads();
    if (tid == 0) {
        float s = 0.f;
        #pragma unroll
        for (int w = 0; w < 8; w++) s += wred[w];
        g_lov_part[t] = s;
    }
}

// ---------------------------------------------------------------------------
// Deterministic final combine (fixed-order double-precision sums)
// ---------------------------------------------------------------------------
__global__ __launch_bounds__(256) void final_kernel(float* __restrict__ out)
{
    const int tid = threadIdx.x;
    __shared__ double red[256];

    double a = 0.0;
    for (int i = tid; i < P1_BLOCKS; i += 256) a += (double)g_bce_part[i];
    red[tid] = a; __syncthreads();
    for (int o = 128; o; o >>= 1) { if (tid < o) red[tid] += red[tid + o]; __syncthreads(); }
    const double bce_sum = red[0]; __syncthreads();

    a = 0.0;
    for (int i = tid; i < P1_BLOCKS; i += 256) a += (double)g_bnd_part[i];
    red[tid] = a; __syncthreads();
    for (int o = 128; o; o >>= 1) { if (tid < o) red[tid] += red[tid + o]; __syncthreads(); }
    const double bnd_sum = red[0]; __syncthreads();

    a = 0.0;
    if (tid < BATCH) {
        double pt = 0.0, ppt = 0.0;
        for (int b = tid * P1_BPI; b < (tid + 1) * P1_BPI; b++) {
            pt  += (double)g_pt_part [b];
            ppt += (double)g_ppt_part[b];
        }
        a = 2.0 * pt / (ppt + EPS_D);
    }
    red[tid] = a; __syncthreads();
    for (int o = 128; o; o >>= 1) { if (tid < o) red[tid] += red[tid + o]; __syncthreads(); }
    const double dice_sum = red[0]; __syncthreads();

    a = 0.0;
    if (tid < BATCH) {
        double lv = 0.0;
        for (int tt = tid * HT_PER_IMG; tt < (tid + 1) * HT_PER_IMG; tt++)
            lv += (double)g_lov_part[tt];
        a = lv;
    }
    red[tid] = a; __syncthreads();
    for (int o = 128; o; o >>= 1) { if (tid < o) red[tid] += red[tid + o]; __syncthreads(); }
    const double lov_sum = red[0];

    if (tid == 0) {
        const double invN = 1.0 / (double)NTOT;
        const double loss = ALPHA * (bce_sum * invN)
                          + BETA  * (1.0 - dice_sum / (double)BATCH)
                          + GAMMA * (bnd_sum * invN)
                          + DELTA * (lov_sum / (double)BATCH);
        out[0] = (float)loss;
    }
}

// ---------------------------------------------------------------------------
// Launch
// ---------------------------------------------------------------------------
extern "C" void kernel_launch(void* const* d_in, const int* in_sizes, int n_in,
                              void* d_out, int out_size)
{
    const float* logits  = (const float*)d_in[0];
    const float* targets = (const float*)d_in[1];

    zero_hist_kernel<<<(BATCH * NB / 4) / 256, 256>>>();
    pass1_kernel    <<<P1_BLOCKS, 128>>>(logits, targets);
    tilecount_kernel<<<NHTILES, 256>>>();
    scan_kernel     <<<1, 1024>>>();
    hlov_kernel     <<<NHTILES, 256>>>();
    final_kernel    <<<1, 256>>>((float*)d_out);
}

// round 12
// speedup vs baseline: 3.5649x; 1.3122x over previous
#include <cuda_runtime.h>
#include <cstdint>
#include <cstddef>

// ---------------------------------------------------------------------------
// Problem constants
// ---------------------------------------------------------------------------
#define IMG_W 512
#define IMG_H 512
#define BATCH 32
#define NPI   (IMG_W * IMG_H)     // 262144 pixels per image
#define NTOT  (BATCH * NPI)       // 8388608 total

#define ALPHA 0.3
#define BETA  0.3
#define GAMMA 0.2
#define DELTA 0.2
#define EPS_D 1e-7

// pass1: one warp per 8-row x 512-wide strip (16 px per lane)
#define STRIP_ROWS 8
#define P1_WARPS   4
#define STRIPS     (BATCH * IMG_H / STRIP_ROWS)   // 2048
#define P1_BLOCKS  (STRIPS / P1_WARPS)            // 512
#define BPI_P1     (P1_BLOCKS / BATCH)            // 16 blocks per image

// histogram: linear buckets over e in (0, 8], reversed (ascending == desc e)
#define NB     32768
#define HSCALE 4096.0f                  // NB / 8
#define HSTEP  2.44140625e-4f           // 8 / NB

// lovasz kernel
#define LT  512                         // threads per image-block
#define BPT (NB / LT)                   // 64 buckets per thread

// ---------------------------------------------------------------------------
// Static device scratch (no allocations allowed).
// g_hist is zero at module load and re-zeroed by lov_kernel every run, so the
// steady-state invariant "hist == 0 before pass1" holds across graph replays.
// ---------------------------------------------------------------------------
__device__ __align__(16) uint32_t g_hist[(size_t)BATCH * NB];   // 4 MB
                                                                // pos<<16 | neg

__device__ float g_bce_part[P1_BLOCKS];
__device__ float g_bnd_part[P1_BLOCKS];
__device__ float g_p_part  [P1_BLOCKS];
__device__ float g_pt_part [P1_BLOCKS];
__device__ int   g_cnt_part[P1_BLOCKS];
__device__ float g_lov_img [BATCH];

// ---------------------------------------------------------------------------
// helpers: 16-wide register rows
// ---------------------------------------------------------------------------
__device__ __forceinline__ void load_row16(const float* __restrict__ base,
                                           int y, int col, bool valid, float* t)
{
    if (valid) {
        const float4* p = reinterpret_cast<const float4*>(base + (size_t)y * IMG_W + col);
        #pragma unroll
        for (int k = 0; k < 4; k++) {
            const float4 v = p[k];
            t[4*k+0] = v.x; t[4*k+1] = v.y; t[4*k+2] = v.z; t[4*k+3] = v.w;
        }
    } else {
        #pragma unroll
        for (int k = 0; k < 16; k++) t[k] = 0.f;
    }
}

// horizontal 3-sum with halo exchange via shuffle (warp spans the full row)
__device__ __forceinline__ void hsum16(const float* t, float* h, int lane)
{
    float left  = __shfl_up_sync  (0xffffffffu, t[15], 1);
    float right = __shfl_down_sync(0xffffffffu, t[0],  1);
    if (lane == 0)  left  = 0.f;
    if (lane == 31) right = 0.f;
    h[0] = left + t[0] + t[1];
    #pragma unroll
    for (int j = 1; j < 15; j++) h[j] = t[j-1] + t[j] + t[j+1];
    h[15] = t[14] + t[15] + right;
}

// ---------------------------------------------------------------------------
// Pass 1: fused BCE + dice partials + boundary BCE + error histogram.
// No shared memory for the stencil; no per-row barriers.
// ---------------------------------------------------------------------------
__global__ __launch_bounds__(128) void pass1_kernel(
    const float* __restrict__ logits, const float* __restrict__ targets)
{
    const int tid  = threadIdx.x;
    const int lane = tid & 31;
    const int warp = tid >> 5;
    const int gw   = blockIdx.x * P1_WARPS + warp;   // strip id
    const int img  = gw >> 6;                         // 64 strips per image
    const int y0   = (gw & 63) * STRIP_ROWS;
    const int col  = lane * 16;

    const float* tg  = targets + (size_t)img * NPI;
    const float* lg  = logits  + (size_t)img * NPI;
    uint32_t*   hist = g_hist  + (size_t)img * NB;

    float tc[16], tn[16], hp[16], hc[16], hn[16];

    load_row16(tg, y0 - 1, col, y0 > 0, tn);
    hsum16(tn, hp, lane);
    load_row16(tg, y0, col, true, tc);
    hsum16(tc, hc, lane);

    float s_bce = 0.f, s_ebce = 0.f, s_p = 0.f, s_pt = 0.f;
    int   s_cnt = 0;

    #pragma unroll 1
    for (int r = 0; r < STRIP_ROWS; r++) {
        const int y = y0 + r;

        load_row16(tg, y + 1, col, (y + 1) < IMG_H, tn);
        hsum16(tn, hn, lane);

        float lx[16];
        load_row16(lg, y, col, true, lx);

        #pragma unroll
        for (int j = 0; j < 16; j++) {
            const float t  = tc[j];
            const float x  = lx[j];
            const float ns = hp[j] + hc[j] + hn[j];     // 3x3 neighbor count
            const bool  yb = (t > 0.5f);

            const float ax  = fabsf(x);
            const float E   = __expf(-ax);              // MUFU.EX2 path
            const float opE = 1.0f + E;
            const float rr  = __fdividef(1.0f, opE);    // MUFU.RCP path
            const float L   = __logf(opE);              // MUFU.LG2 path

            const float bce = fmaxf(x, 0.f) - x * t + L;
            s_bce += bce;
            if (ns > 0.5f && ns < 8.5f) s_ebce += bce;  // edge weight 3 = 1 + 2

            const float p = (x >= 0.f) ? rr : (1.0f - rr);
            s_p += p;
            if (yb) { s_pt += p; s_cnt++; }

            const float e = yb ? (1.0f - x) : (1.0f + x);
            if (e > 0.0f) {
                int b = (int)(e * HSCALE);
                b = min(b, NB - 1);
                atomicAdd(&hist[(NB - 1) - b], yb ? 0x10000u : 1u);
            }
        }

        #pragma unroll
        for (int j = 0; j < 16; j++) { hp[j] = hc[j]; hc[j] = hn[j]; tc[j] = tn[j]; }
    }

    // block reduce (4 warps)
    #pragma unroll
    for (int o = 16; o; o >>= 1) {
        s_bce  += __shfl_down_sync(0xffffffffu, s_bce,  o);
        s_ebce += __shfl_down_sync(0xffffffffu, s_ebce, o);
        s_p    += __shfl_down_sync(0xffffffffu, s_p,    o);
        s_pt   += __shfl_down_sync(0xffffffffu, s_pt,   o);
        s_cnt  += __shfl_down_sync(0xffffffffu, s_cnt,  o);
    }
    __shared__ float4 wred[4];
    __shared__ int    wcnt[4];
    if (lane == 0) { wred[warp] = make_float4(s_bce, s_ebce, s_p, s_pt); wcnt[warp] = s_cnt; }
    __syncthreads();
    if (tid == 0) {
        float4 s = wred[0];
        int    c = wcnt[0];
        for (int w = 1; w < 4; w++) {
            s.x += wred[w].x; s.y += wred[w].y; s.z += wred[w].z; s.w += wred[w].w;
            c += wcnt[w];
        }
        g_bce_part[blockIdx.x] = s.x;
        g_bnd_part[blockIdx.x] = s.x + 2.0f * s.y;    // weight 3 on edges
        g_p_part  [blockIdx.x] = s.z;
        g_pt_part [blockIdx.x] = s.w;
        g_cnt_part[blockIdx.x] = c;
    }
}

// ---------------------------------------------------------------------------
// Lovasz: one block per image. Reads the image's histogram, block-scans
// (pos, tot), evaluates the closed-form per-bucket contributions, zeroes the
// histogram for the next replay.
//   positives run : U = G + i0 - c0 constant  -> e * n1 / U
//   negatives run : telescoping               -> e * (G-c) * n0 / (a*(a+n0))
// ---------------------------------------------------------------------------
__global__ __launch_bounds__(LT) void lov_kernel()
{
    const int im   = blockIdx.x;
    const int tid  = threadIdx.x;
    const int lane = tid & 31;
    const int warp = tid >> 5;                    // 16 warps

    uint32_t* h = g_hist + (size_t)im * NB + (size_t)tid * BPT;

    uint32_t v[BPT];
    #pragma unroll
    for (int k = 0; k < BPT / 4; k++) {
        const uint4 q = reinterpret_cast<uint4*>(h)[k];
        v[4*k+0] = q.x; v[4*k+1] = q.y; v[4*k+2] = q.z; v[4*k+3] = q.w;
    }
    #pragma unroll
    for (int k = 0; k < BPT / 4; k++)
        reinterpret_cast<uint4*>(h)[k] = make_uint4(0u, 0u, 0u, 0u);

    // per-thread totals, packed (tot << 32 | pos)
    int tp = 0, tt = 0;
    #pragma unroll
    for (int j = 0; j < BPT; j++) {
        const int p = (int)(v[j] >> 16), n = (int)(v[j] & 0xffffu);
        tp += p; tt += p + n;
    }
    unsigned long long pk  = ((unsigned long long)(unsigned)tt << 32) | (unsigned)tp;
    unsigned long long inc = pk;
    #pragma unroll
    for (int o = 1; o < 32; o <<= 1) {
        const unsigned long long nv = __shfl_up_sync(0xffffffffu, inc, o);
        if (lane >= o) inc += nv;
    }
    __shared__ unsigned long long wtot[16];
    __shared__ int sG;
    if (lane == 31) wtot[warp] = inc;

    // G = total positives of this image (sum of 16 pass1 block counts)
    if (warp == 0) {
        int c = (lane < BPI_P1) ? g_cnt_part[im * BPI_P1 + lane] : 0;
        #pragma unroll
        for (int o = 8; o; o >>= 1) c += __shfl_down_sync(0xffffffffu, c, o);
        if (lane == 0) sG = c;
    }
    __syncthreads();

    unsigned long long woff = 0;
    for (int w = 0; w < warp; w++) woff += wtot[w];
    const unsigned long long excl = woff + inc - pk;

    const int G = sG;
    int i0 = (int)(excl >> 32);
    int c0 = (int)(excl & 0xffffffffu);

    const int rb0 = tid * BPT;
    float acc = 0.f;

    #pragma unroll
    for (int j = 0; j < BPT; j++) {
        const int n1 = (int)(v[j] >> 16), n0 = (int)(v[j] & 0xffffu);
        const int n = n1 + n0;
        if (n) {
            const int   b = (NB - 1) - (rb0 + j);
            const float e = ((float)b + 0.5f) * HSTEP;

            if (G == 0 && i0 == 0) acc += e;            // degenerate image
            if (n1) acc += e * (float)n1 / (float)(G + i0 - c0);
            const int c  = c0 + n1;
            const int Gc = G - c;
            if (n0 && Gc > 0) {
                const float aU = (float)(G + i0 + n1 - c);
                acc += e * (float)Gc * (float)n0 / (aU * (aU + (float)n0));
            }
            i0 += n; c0 += n1;
        }
    }

    #pragma unroll
    for (int o = 16; o; o >>= 1) acc += __shfl_down_sync(0xffffffffu, acc, o);
    __shared__ float wred[16];
    if (lane == 0) wred[warp] = acc;
    __syncthreads();
    if (tid == 0) {
        float s = 0.f;
        #pragma unroll
        for (int w = 0; w < 16; w++) s += wred[w];
        g_lov_img[im] = s;
    }
}

// ---------------------------------------------------------------------------
// Deterministic final combine (fixed-order double-precision sums)
// ---------------------------------------------------------------------------
__global__ __launch_bounds__(256) void final_kernel(float* __restrict__ out)
{
    const int tid = threadIdx.x;
    __shared__ double red[256];

    double a = 0.0;
    for (int i = tid; i < P1_BLOCKS; i += 256) a += (double)g_bce_part[i];
    red[tid] = a; __syncthreads();
    for (int o = 128; o; o >>= 1) { if (tid < o) red[tid] += red[tid + o]; __syncthreads(); }
    const double bce_sum = red[0]; __syncthreads();

    a = 0.0;
    for (int i = tid; i < P1_BLOCKS; i += 256) a += (double)g_bnd_part[i];
    red[tid] = a; __syncthreads();
    for (int o = 128; o; o >>= 1) { if (tid < o) red[tid] += red[tid + o]; __syncthreads(); }
    const double bnd_sum = red[0]; __syncthreads();

    // dice: per-image 2*sum(p*t) / (sum(p) + sum(t) + eps)
    a = 0.0;
    if (tid < BATCH) {
        double pt = 0.0, pp = 0.0; long long cnt = 0;
        for (int b = tid * BPI_P1; b < (tid + 1) * BPI_P1; b++) {
            pt  += (double)g_pt_part [b];
            pp  += (double)g_p_part  [b];
            cnt += (long long)g_cnt_part[b];
        }
        a = 2.0 * pt / (pp + (double)cnt + EPS_D);
    }
    red[tid] = a; __syncthreads();
    for (int o = 128; o; o >>= 1) { if (tid < o) red[tid] += red[tid + o]; __syncthreads(); }
    const double dice_sum = red[0]; __syncthreads();

    a = (tid < BATCH) ? (double)g_lov_img[tid] : 0.0;
    red[tid] = a; __syncthreads();
    for (int o = 128; o; o >>= 1) { if (tid < o) red[tid] += red[tid + o]; __syncthreads(); }
    const double lov_sum = red[0];

    if (tid == 0) {
        const double invN = 1.0 / (double)NTOT;
        const double loss = ALPHA * (bce_sum * invN)
                          + BETA  * (1.0 - dice_sum / (double)BATCH)
                          + GAMMA * (bnd_sum * invN)
                          + DELTA * (lov_sum / (double)BATCH);
        out[0] = (float)loss;
    }
}

// ---------------------------------------------------------------------------
// Launch: 3 kernels. Histogram zeroing is maintained by lov_kernel itself
// (zero at module load, re-zeroed after each read), so the invariant holds
// across graph replays.
// ---------------------------------------------------------------------------
extern "C" void kernel_launch(void* const* d_in, const int* in_sizes, int n_in,
                              void* d_out, int out_size)
{
    const float* logits  = (const float*)d_in[0];
    const float* targets = (const float*)d_in[1];

    pass1_kernel<<<P1_BLOCKS, 128>>>(logits, targets);
    lov_kernel  <<<BATCH, LT>>>();
    final_kernel<<<1, 256>>>((float*)d_out);
}

// round 13
// speedup vs baseline: 7.5912x; 2.1294x over previous
#include <cuda_runtime.h>
#include <cstdint>
#include <cstddef>

// ---------------------------------------------------------------------------
// Problem constants
// ---------------------------------------------------------------------------
#define IMG_W 512
#define IMG_H 512
#define BATCH 32
#define NPI   (IMG_W * IMG_H)     // 262144 pixels per image
#define NTOT  (BATCH * NPI)       // 8388608 total

#define ALPHA 0.3
#define BETA  0.3
#define GAMMA 0.2
#define DELTA 0.2
#define EPS_D 1e-7

// pass1: 256 threads = 8 warps; warp = 8-row x 512-wide strip; block = 64 rows
#define STRIP_ROWS 8
#define P1_WARPS   8
#define NPART      8                              // blocks per image
#define P1_BLOCKS  (BATCH * NPART)                // 256
#define P1_TPB     256

// histogram: linear buckets over e in (0, 8], reversed (ascending == desc e)
#define NB     8192
#define HSCALE 1024.0f                  // NB / 8
#define HSTEP  9.765625e-4f             // 8 / NB

// lovasz kernel
#define LT  512                         // threads per image-block
#define BPT (NB / LT)                   // 16 buckets per thread

// ---------------------------------------------------------------------------
// Static device scratch (no allocations allowed).
// g_hist_part is fully overwritten by pass1 every launch (plain stores), so
// no zeroing pass and no cross-replay state.
// Layout: [image*NPART + part][NB], packed pos<<16 | neg (per-block <= 32768).
// ---------------------------------------------------------------------------
__device__ __align__(16) uint32_t g_hist_part[(size_t)P1_BLOCKS * NB];  // 8 MB

__device__ float g_bce_part[P1_BLOCKS];
__device__ float g_bnd_part[P1_BLOCKS];
__device__ float g_p_part  [P1_BLOCKS];
__device__ float g_pt_part [P1_BLOCKS];
__device__ int   g_cnt_part[P1_BLOCKS];
__device__ float g_lov_img [BATCH];

// ---------------------------------------------------------------------------
// helpers: 16-wide register rows
// ---------------------------------------------------------------------------
__device__ __forceinline__ void load_row16(const float* __restrict__ base,
                                           int y, int col, bool valid, float* t)
{
    if (valid) {
        const float4* p = reinterpret_cast<const float4*>(base + (size_t)y * IMG_W + col);
        #pragma unroll
        for (int k = 0; k < 4; k++) {
            const float4 v = p[k];
            t[4*k+0] = v.x; t[4*k+1] = v.y; t[4*k+2] = v.z; t[4*k+3] = v.w;
        }
    } else {
        #pragma unroll
        for (int k = 0; k < 16; k++) t[k] = 0.f;
    }
}

// horizontal 3-sum with halo exchange via shuffle (warp spans the full row)
__device__ __forceinline__ void hsum16(const float* v, float* h, int lane)
{
    float left  = __shfl_up_sync  (0xffffffffu, v[15], 1);
    float right = __shfl_down_sync(0xffffffffu, v[0],  1);
    if (lane == 0)  left  = 0.f;
    if (lane == 31) right = 0.f;
    h[0] = left + v[0] + v[1];
    #pragma unroll
    for (int j = 1; j < 15; j++) h[j] = v[j-1] + v[j] + v[j+1];
    h[15] = v[14] + v[15] + right;
}

// ---------------------------------------------------------------------------
// Pass 1: fused BCE + dice partials + boundary BCE + smem error histogram.
// ---------------------------------------------------------------------------
__global__ __launch_bounds__(P1_TPB, 2) void pass1_kernel(
    const float* __restrict__ logits, const float* __restrict__ targets)
{
    __shared__ uint32_t sh[NB];                   // 32 KB private histogram

    const int tid  = threadIdx.x;
    const int lane = tid & 31;
    const int warp = tid >> 5;
    const int blk  = blockIdx.x;
    const int img  = blk >> 3;                    // / NPART
    const int y0   = (blk & 7) * 64 + warp * STRIP_ROWS;
    const int col  = lane * 16;

    // zero the private histogram
    #pragma unroll
    for (int i = tid; i < NB / 4; i += P1_TPB)
        reinterpret_cast<uint4*>(sh)[i] = make_uint4(0u, 0u, 0u, 0u);
    __syncthreads();

    const float* tg = targets + (size_t)img * NPI;
    const float* lg = logits  + (size_t)img * NPI;

    // rolling target rows (vertical-sum-first stencil)
    float tp[16], tc[16], tn[16];
    load_row16(tg, y0 - 1, col, y0 > 0, tp);
    load_row16(tg, y0,     col, true,   tc);

    float s_bce = 0.f, s_ebce = 0.f, s_p = 0.f, s_pt = 0.f;
    int   s_cnt = 0;

    #pragma unroll 1
    for (int r = 0; r < STRIP_ROWS; r++) {
        const int y = y0 + r;

        load_row16(tg, y + 1, col, (y + 1) < IMG_H, tn);

        float lx[16];
        load_row16(lg, y, col, true, lx);

        float vsum[16], h[16];
        #pragma unroll
        for (int j = 0; j < 16; j++) vsum[j] = tp[j] + tc[j] + tn[j];
        hsum16(vsum, h, lane);

        #pragma unroll
        for (int j = 0; j < 16; j++) {
            const float t  = tc[j];
            const float x  = lx[j];
            const float ns = h[j];                  // 3x3 neighbor count
            const bool  yb = (t > 0.5f);

            const float ax  = fabsf(x);
            const float E   = __expf(-ax);          // MUFU.EX2 path
            const float opE = 1.0f + E;
            const float rr  = __fdividef(1.0f, opE);// MUFU.RCP path
            const float L   = __logf(opE);          // MUFU.LG2 path

            const float bce = fmaxf(x, 0.f) - x * t + L;
            s_bce += bce;
            if (ns > 0.5f && ns < 8.5f) s_ebce += bce;   // edge weight 3 = 1 + 2

            const float p = (x >= 0.f) ? rr : (1.0f - rr);
            s_p += p;
            if (yb) { s_pt += p; s_cnt++; }

            const float e = yb ? (1.0f - x) : (1.0f + x);
            if (e > 0.0f) {
                int b = (int)(e * HSCALE);
                b = min(b, NB - 1);
                atomicAdd(&sh[(NB - 1) - b], yb ? 0x10000u : 1u);
            }
        }

        #pragma unroll
        for (int j = 0; j < 16; j++) { tp[j] = tc[j]; tc[j] = tn[j]; }
    }

    // block reduce (8 warps)
    #pragma unroll
    for (int o = 16; o; o >>= 1) {
        s_bce  += __shfl_down_sync(0xffffffffu, s_bce,  o);
        s_ebce += __shfl_down_sync(0xffffffffu, s_ebce, o);
        s_p    += __shfl_down_sync(0xffffffffu, s_p,    o);
        s_pt   += __shfl_down_sync(0xffffffffu, s_pt,   o);
        s_cnt  += __shfl_down_sync(0xffffffffu, s_cnt,  o);
    }
    __shared__ float4 wred[P1_WARPS];
    __shared__ int    wcnt[P1_WARPS];
    if (lane == 0) { wred[warp] = make_float4(s_bce, s_ebce, s_p, s_pt); wcnt[warp] = s_cnt; }
    __syncthreads();

    // flush private histogram to this block's partial region (plain stores)
    uint32_t* dst = g_hist_part + (size_t)blk * NB;
    #pragma unroll
    for (int i = tid; i < NB / 4; i += P1_TPB)
        reinterpret_cast<uint4*>(dst)[i] = reinterpret_cast<const uint4*>(sh)[i];

    if (tid == 0) {
        float4 s = wred[0];
        int    c = wcnt[0];
        #pragma unroll
        for (int w = 1; w < P1_WARPS; w++) {
            s.x += wred[w].x; s.y += wred[w].y; s.z += wred[w].z; s.w += wred[w].w;
            c += wcnt[w];
        }
        g_bce_part[blk] = s.x;
        g_bnd_part[blk] = s.x + 2.0f * s.y;        // weight 3 on edges
        g_p_part  [blk] = s.z;
        g_pt_part [blk] = s.w;
        g_cnt_part[blk] = c;
    }
}

// ---------------------------------------------------------------------------
// Lovasz: one block per image. Sums the NPART partial histograms, block-scans
// (pos, tot), then evaluates closed-form per-bucket contributions.
//   positives run : U = G + i0 - c0 constant  -> e * n1 / U
//   negatives run : telescoping               -> e * (G-c) * n0 / (a*(a+n0))
// ---------------------------------------------------------------------------
__global__ __launch_bounds__(LT) void lov_kernel()
{
    const int im   = blockIdx.x;
    const int tid  = threadIdx.x;
    const int lane = tid & 31;
    const int warp = tid >> 5;                    // 16 warps

    // gather this thread's BPT buckets from all NPART partials
    int pos[BPT], neg[BPT];
    #pragma unroll
    for (int j = 0; j < BPT; j++) { pos[j] = 0; neg[j] = 0; }

    #pragma unroll
    for (int b = 0; b < NPART; b++) {
        const uint4* src = reinterpret_cast<const uint4*>(
            g_hist_part + (size_t)(im * NPART + b) * NB + (size_t)tid * BPT);
        #pragma unroll
        for (int k = 0; k < BPT / 4; k++) {
            const uint4 q = src[k];
            pos[4*k+0] += (int)(q.x >> 16); neg[4*k+0] += (int)(q.x & 0xffffu);
            pos[4*k+1] += (int)(q.y >> 16); neg[4*k+1] += (int)(q.y & 0xffffu);
            pos[4*k+2] += (int)(q.z >> 16); neg[4*k+2] += (int)(q.z & 0xffffu);
            pos[4*k+3] += (int)(q.w >> 16); neg[4*k+3] += (int)(q.w & 0xffffu);
        }
    }

    // per-thread totals, packed (tot << 32 | pos); block exclusive scan
    int tp = 0, tt = 0;
    #pragma unroll
    for (int j = 0; j < BPT; j++) { tp += pos[j]; tt += pos[j] + neg[j]; }

    unsigned long long pk  = ((unsigned long long)(unsigned)tt << 32) | (unsigned)tp;
    unsigned long long inc = pk;
    #pragma unroll
    for (int o = 1; o < 32; o <<= 1) {
        const unsigned long long nv = __shfl_up_sync(0xffffffffu, inc, o);
        if (lane >= o) inc += nv;
    }
    __shared__ unsigned long long wtot[LT / 32];
    __shared__ int sG;
    if (lane == 31) wtot[warp] = inc;

    // G = total positives of this image
    if (warp == 0) {
        int c = (lane < NPART) ? g_cnt_part[im * NPART + lane] : 0;
        #pragma unroll
        for (int o = 8; o; o >>= 1) c += __shfl_down_sync(0xffffffffu, c, o);
        if (lane == 0) sG = c;
    }
    __syncthreads();

    unsigned long long woff = 0;
    for (int w = 0; w < warp; w++) woff += wtot[w];
    const unsigned long long excl = woff + inc - pk;

    const int G = sG;
    int i0 = (int)(excl >> 32);
    int c0 = (int)(excl & 0xffffffffu);

    const int rb0 = tid * BPT;
    float acc = 0.f;

    #pragma unroll
    for (int j = 0; j < BPT; j++) {
        const int n1 = pos[j], n0 = neg[j];
        const int n = n1 + n0;
        if (n) {
            const int   b = (NB - 1) - (rb0 + j);
            const float e = ((float)b + 0.5f) * HSTEP;

            if (G == 0 && i0 == 0) acc += e;            // degenerate image
            if (n1) acc += e * (float)n1 / (float)(G + i0 - c0);
            const int c  = c0 + n1;
            const int Gc = G - c;
            if (n0 && Gc > 0) {
                const float aU = (float)(G + i0 + n1 - c);
                acc += e * (float)Gc * (float)n0 / (aU * (aU + (float)n0));
            }
            i0 += n; c0 += n1;
        }
    }

    #pragma unroll
    for (int o = 16; o; o >>= 1) acc += __shfl_down_sync(0xffffffffu, acc, o);
    __shared__ float wred[LT / 32];
    if (lane == 0) wred[warp] = acc;
    __syncthreads();
    if (tid == 0) {
        float s = 0.f;
        #pragma unroll
        for (int w = 0; w < LT / 32; w++) s += wred[w];
        g_lov_img[im] = s;
    }
}

// ---------------------------------------------------------------------------
// Deterministic final combine (fixed-order double-precision sums)
// ---------------------------------------------------------------------------
__global__ __launch_bounds__(256) void final_kernel(float* __restrict__ out)
{
    const int tid = threadIdx.x;
    __shared__ double red[256];

    double a = 0.0;
    for (int i = tid; i < P1_BLOCKS; i += 256) a += (double)g_bce_part[i];
    red[tid] = a; __syncthreads();
    for (int o = 128; o; o >>= 1) { if (tid < o) red[tid] += red[tid + o]; __syncthreads(); }
    const double bce_sum = red[0]; __syncthreads();

    a = 0.0;
    for (int i = tid; i < P1_BLOCKS; i += 256) a += (double)g_bnd_part[i];
    red[tid] = a; __syncthreads();
    for (int o = 128; o; o >>= 1) { if (tid < o) red[tid] += red[tid + o]; __syncthreads(); }
    const double bnd_sum = red[0]; __syncthreads();

    // dice: per-image 2*sum(p*t) / (sum(p) + sum(t) + eps)
    a = 0.0;
    if (tid < BATCH) {
        double pt = 0.0, pp = 0.0; long long cnt = 0;
        for (int b = tid * NPART; b < (tid + 1) * NPART; b++) {
            pt  += (double)g_pt_part [b];
            pp  += (double)g_p_part  [b];
            cnt += (long long)g_cnt_part[b];
        }
        a = 2.0 * pt / (pp + (double)cnt + EPS_D);
    }
    red[tid] = a; __syncthreads();
    for (int o = 128; o; o >>= 1) { if (tid < o) red[tid] += red[tid + o]; __syncthreads(); }
    const double dice_sum = red[0]; __syncthreads();

    a = (tid < BATCH) ? (double)g_lov_img[tid] : 0.0;
    red[tid] = a; __syncthreads();
    for (int o = 128; o; o >>= 1) { if (tid < o) red[tid] += red[tid + o]; __syncthreads(); }
    const double lov_sum = red[0];

    if (tid == 0) {
        const double invN = 1.0 / (double)NTOT;
        const double loss = ALPHA * (bce_sum * invN)
                          + BETA  * (1.0 - dice_sum / (double)BATCH)
                          + GAMMA * (bnd_sum * invN)
                          + DELTA * (lov_sum / (double)BATCH);
        out[0] = (float)loss;
    }
}

// ---------------------------------------------------------------------------
// Launch: 3 kernels, no global atomics, no zeroing pass (partial histograms
// are fully overwritten each launch -> graph-replay safe).
// ---------------------------------------------------------------------------
extern "C" void kernel_launch(void* const* d_in, const int* in_sizes, int n_in,
                              void* d_out, int out_size)
{
    const float* logits  = (const float*)d_in[0];
    const float* targets = (const float*)d_in[1];

    pass1_kernel<<<P1_BLOCKS, P1_TPB>>>(logits, targets);
    lov_kernel  <<<BATCH, LT>>>();
    final_kernel<<<1, 256>>>((float*)d_out);
}

// round 15
// speedup vs baseline: 8.4762x; 1.1166x over previous
#include <cuda_runtime.h>
#include <cstdint>
#include <cstddef>

// ---------------------------------------------------------------------------
// Problem constants
// ---------------------------------------------------------------------------
#define IMG_W 512
#define IMG_H 512
#define BATCH 32
#define NPI   (IMG_W * IMG_H)     // 262144 pixels per image
#define NTOT  (BATCH * NPI)       // 8388608 total

#define ALPHA 0.3
#define BETA  0.3
#define GAMMA 0.2
#define DELTA 0.2
#define EPS_D 1e-7

// pass1: 256 threads = 8 warps. Each warp: 16-row x 256-col strip (8 px/lane).
// Image = 32 row-bands x 2 column-segments = 64 warp-strips; 8 strips/block.
#define STRIP_ROWS 16
#define P1_WARPS   8
#define NPART      8                              // blocks per image
#define P1_BLOCKS  (BATCH * NPART)                // 256
#define P1_TPB     256

// histogram: linear buckets over e in (0, 8], reversed (ascending == desc e)
#define NB     4096
#define HSCALE 512.0f                   // NB / 8
#define HSTEP  1.953125e-3f             // 8 / NB

// lovasz kernel
#define LT  512                         // threads per image-block
#define BPT (NB / LT)                   // 8 buckets per thread

// ---------------------------------------------------------------------------
// Static device scratch (no allocations allowed).
// g_hist_part fully overwritten by pass1 each launch (plain stores) -> no
// zeroing pass, graph-replay safe. Layout [img*NPART+part][NB], pos<<16|neg.
// ---------------------------------------------------------------------------
__device__ __align__(16) uint32_t g_hist_part[(size_t)P1_BLOCKS * NB];  // 4 MB

__device__ float g_bce_part[P1_BLOCKS];
__device__ float g_bnd_part[P1_BLOCKS];
__device__ float g_p_part  [P1_BLOCKS];
__device__ float g_pt_part [P1_BLOCKS];
__device__ int   g_cnt_part[P1_BLOCKS];
__device__ float g_lov_img [BATCH];
__device__ int   g_done;                 // zero-init; last lov block resets it

// ---------------------------------------------------------------------------
// helpers: 8-wide register rows
// ---------------------------------------------------------------------------
__device__ __forceinline__ void load_row8(const float* __restrict__ base,
                                          int y, int col, bool valid, float* t)
{
    if (valid) {
        const float4* p = reinterpret_cast<const float4*>(base + (size_t)y * IMG_W + col);
        const float4 a = p[0], b = p[1];
        t[0] = a.x; t[1] = a.y; t[2] = a.z; t[3] = a.w;
        t[4] = b.x; t[5] = b.y; t[6] = b.z; t[7] = b.w;
    } else {
        #pragma unroll
        for (int k = 0; k < 8; k++) t[k] = 0.f;
    }
}

// ---------------------------------------------------------------------------
// Pass 1: fused BCE + dice partials + boundary BCE + smem error histogram.
// Register-resident 3x3 stencil; warp-edge column halo via 1 scalar load/row
// on lanes 0/31 (rolled vertically like the main rows).
// ---------------------------------------------------------------------------
__global__ __launch_bounds__(P1_TPB, 3) void pass1_kernel(
    const float* __restrict__ logits, const float* __restrict__ targets)
{
    __shared__ uint32_t sh[NB];                   // 16 KB private histogram

    const int tid  = threadIdx.x;
    const int lane = tid & 31;
    const int warp = tid >> 5;
    const int blk  = blockIdx.x;
    const int img  = blk >> 3;                    // / NPART
    const int part = blk & 7;
    const int strip = part * P1_WARPS + warp;     // 0..63
    const int seg   = strip & 1;                  // column segment (0 or 1)
    const int band  = strip >> 1;                 // row band (0..31)
    const int y0    = band * STRIP_ROWS;
    const int col   = seg * 256 + lane * 8;

    // zero private histogram
    #pragma unroll
    for (int i = tid; i < NB / 4; i += P1_TPB)
        reinterpret_cast<uint4*>(sh)[i] = make_uint4(0u, 0u, 0u, 0u);
    __syncthreads();

    const float* tg = targets + (size_t)img * NPI;
    const float* lg = logits  + (size_t)img * NPI;

    // halo column x for this lane (-1 = image border / unused lane)
    int hx = -1;
    if (lane == 0  && seg == 1) hx = 255;
    if (lane == 31 && seg == 0) hx = 256;

    float tp[8], tc[8], tn[8];
    float hhp = 0.f, hhc = 0.f;
    load_row8(tg, y0 - 1, col, y0 > 0, tp);
    load_row8(tg, y0,     col, true,   tc);
    if (hx >= 0) {
        if (y0 > 0) hhp = tg[(size_t)(y0 - 1) * IMG_W + hx];
        hhc = tg[(size_t)y0 * IMG_W + hx];
    }

    float s_bce = 0.f, s_ebce = 0.f, s_p = 0.f, s_pt = 0.f;
    int   s_cnt = 0;

    #pragma unroll 1
    for (int r = 0; r < STRIP_ROWS; r++) {
        const int  y  = y0 + r;
        const bool vn = (y + 1) < IMG_H;

        load_row8(tg, y + 1, col, vn, tn);
        const float hhn = (hx >= 0 && vn) ? tg[(size_t)(y + 1) * IMG_W + hx] : 0.f;

        float lx[8];
        load_row8(lg, y, col, true, lx);

        // vertical 3-sums, then horizontal 3-sum via shuffle + halo
        float vs[8];
        #pragma unroll
        for (int j = 0; j < 8; j++) vs[j] = tp[j] + tc[j] + tn[j];
        const float vh = hhp + hhc + hhn;

        float left  = __shfl_up_sync  (0xffffffffu, vs[7], 1);
        float right = __shfl_down_sync(0xffffffffu, vs[0], 1);
        if (lane == 0)  left  = vh;   // 0 at the true image border (hx<0)
        if (lane == 31) right = vh;

        float h[8];
        h[0] = left + vs[0] + vs[1];
        #pragma unroll
        for (int j = 1; j < 7; j++) h[j] = vs[j-1] + vs[j] + vs[j+1];
        h[7] = vs[6] + vs[7] + right;

        #pragma unroll
        for (int j = 0; j < 8; j++) {
            const float t  = tc[j];
            const float x  = lx[j];
            const float ns = h[j];                  // 3x3 neighbor count
            const bool  yb = (t > 0.5f);

            const float ax  = fabsf(x);
            const float E   = __expf(-ax);          // MUFU.EX2
            const float opE = 1.0f + E;
            const float rr  = __fdividef(1.0f, opE);// MUFU.RCP
            const float L   = __logf(opE);          // MUFU.LG2

            const float bce = fmaxf(x, 0.f) - x * t + L;
            s_bce += bce;
            if (ns > 0.5f && ns < 8.5f) s_ebce += bce;   // edge weight 3 = 1+2

            const float p = (x >= 0.f) ? rr : (1.0f - rr);
            s_p += p;
            if (yb) { s_pt += p; s_cnt++; }

            const float e = yb ? (1.0f - x) : (1.0f + x);
            if (e > 0.0f) {
                int b = (int)(e * HSCALE);
                b = min(b, NB - 1);
                atomicAdd(&sh[(NB - 1) - b], yb ? 0x10000u : 1u);
            }
        }

        #pragma unroll
        for (int j = 0; j < 8; j++) { tp[j] = tc[j]; tc[j] = tn[j]; }
        hhp = hhc; hhc = hhn;
    }

    // block reduce (8 warps)
    #pragma unroll
    for (int o = 16; o; o >>= 1) {
        s_bce  += __shfl_down_sync(0xffffffffu, s_bce,  o);
        s_ebce += __shfl_down_sync(0xffffffffu, s_ebce, o);
        s_p    += __shfl_down_sync(0xffffffffu, s_p,    o);
        s_pt   += __shfl_down_sync(0xffffffffu, s_pt,   o);
        s_cnt  += __shfl_down_sync(0xffffffffu, s_cnt,  o);
    }
    __shared__ float4 wred[P1_WARPS];
    __shared__ int    wcnt[P1_WARPS];
    if (lane == 0) { wred[warp] = make_float4(s_bce, s_ebce, s_p, s_pt); wcnt[warp] = s_cnt; }
    __syncthreads();

    // flush private histogram (plain stores, no atomics)
    uint32_t* dst = g_hist_part + (size_t)blk * NB;
    #pragma unroll
    for (int i = tid; i < NB / 4; i += P1_TPB)
        reinterpret_cast<uint4*>(dst)[i] = reinterpret_cast<const uint4*>(sh)[i];

    if (tid == 0) {
        float4 s = wred[0];
        int    c = wcnt[0];
        #pragma unroll
        for (int w = 1; w < P1_WARPS; w++) {
            s.x += wred[w].x; s.y += wred[w].y; s.z += wred[w].z; s.w += wred[w].w;
            c += wcnt[w];
        }
        g_bce_part[blk] = s.x;
        g_bnd_part[blk] = s.x + 2.0f * s.y;        // weight 3 on edges
        g_p_part  [blk] = s.z;
        g_pt_part [blk] = s.w;
        g_cnt_part[blk] = c;
    }
}

// ---------------------------------------------------------------------------
// Lovasz (one block per image) + fused final combine (last block to finish).
//   positives run : U = G + i0 - c0 constant  -> e * n1 / U
//   negatives run : telescoping               -> e * (G-c) * n0 / (a*(a+n0))
// ---------------------------------------------------------------------------
__global__ __launch_bounds__(LT) void lov_kernel(float* __restrict__ out)
{
    const int im   = blockIdx.x;
    const int tid  = threadIdx.x;
    const int lane = tid & 31;
    const int warp = tid >> 5;                    // 16 warps

    // gather this thread's BPT buckets from all NPART partials
    int pos[BPT], neg[BPT];
    #pragma unroll
    for (int j = 0; j < BPT; j++) { pos[j] = 0; neg[j] = 0; }

    #pragma unroll
    for (int b = 0; b < NPART; b++) {
        const uint4* src = reinterpret_cast<const uint4*>(
            g_hist_part + (size_t)(im * NPART + b) * NB + (size_t)tid * BPT);
        #pragma unroll
        for (int k = 0; k < BPT / 4; k++) {
            const uint4 q = src[k];
            pos[4*k+0] += (int)(q.x >> 16); neg[4*k+0] += (int)(q.x & 0xffffu);
            pos[4*k+1] += (int)(q.y >> 16); neg[4*k+1] += (int)(q.y & 0xffffu);
            pos[4*k+2] += (int)(q.z >> 16); neg[4*k+2] += (int)(q.z & 0xffffu);
            pos[4*k+3] += (int)(q.w >> 16); neg[4*k+3] += (int)(q.w & 0xffffu);
        }
    }

    // per-thread totals packed (tot << 32 | pos); block exclusive scan
    int tp = 0, tt = 0;
    #pragma unroll
    for (int j = 0; j < BPT; j++) { tp += pos[j]; tt += pos[j] + neg[j]; }

    unsigned long long pk  = ((unsigned long long)(unsigned)tt << 32) | (unsigned)tp;
    unsigned long long inc = pk;
    #pragma unroll
    for (int o = 1; o < 32; o <<= 1) {
        const unsigned long long nv = __shfl_up_sync(0xffffffffu, inc, o);
        if (lane >= o) inc += nv;
    }
    __shared__ unsigned long long wtot[LT / 32];
    __shared__ int sG;
    if (lane == 31) wtot[warp] = inc;

    // G = total positives of this image
    if (warp == 0) {
        int c = (lane < NPART) ? g_cnt_part[im * NPART + lane] : 0;
        #pragma unroll
        for (int o = 16; o; o >>= 1) c += __shfl_down_sync(0xffffffffu, c, o);
        if (lane == 0) sG = c;
    }
    __syncthreads();

    unsigned long long woff = 0;
    for (int w = 0; w < warp; w++) woff += wtot[w];
    const unsigned long long excl = woff + inc - pk;

    const int G = sG;
    int i0 = (int)(excl >> 32);
    int c0 = (int)(excl & 0xffffffffu);

    const int rb0 = tid * BPT;
    float acc = 0.f;

    #pragma unroll
    for (int j = 0; j < BPT; j++) {
        const int n1 = pos[j], n0 = neg[j];
        const int n = n1 + n0;
        if (n) {
            const int   b = (NB - 1) - (rb0 + j);
            const float e = ((float)b + 0.5f) * HSTEP;

            if (G == 0 && i0 == 0) acc += e;            // degenerate image
            if (n1) acc += e * (float)n1 / (float)(G + i0 - c0);
            const int c  = c0 + n1;
            const int Gc = G - c;
            if (n0 && Gc > 0) {
                const float aU = (float)(G + i0 + n1 - c);
                acc += e * (float)Gc * (float)n0 / (aU * (aU + (float)n0));
            }
            i0 += n; c0 += n1;
        }
    }

    #pragma unroll
    for (int o = 16; o; o >>= 1) acc += __shfl_down_sync(0xffffffffu, acc, o);
    __shared__ float wred[LT / 32];
    if (lane == 0) wred[warp] = acc;
    __syncthreads();
    if (tid == 0) {
        float s = 0.f;
        #pragma unroll
        for (int w = 0; w < LT / 32; w++) s += wred[w];
        g_lov_img[im] = s;
    }

    // ---- last-block final combine (deterministic fixed-order sums) ----
    __shared__ bool s_last;
    if (tid == 0) {
        __threadfence();
        s_last = (atomicAdd(&g_done, 1) == BATCH - 1);
    }
    __syncthreads();
    if (!s_last) return;
    __threadfence();

    __shared__ double red[LT];

    double a = 0.0;
    for (int i = tid; i < P1_BLOCKS; i += LT) a += (double)g_bce_part[i];
    red[tid] = a; __syncthreads();
    for (int o = LT / 2; o; o >>= 1) { if (tid < o) red[tid] += red[tid + o]; __syncthreads(); }
    const double bce_sum = red[0]; __syncthreads();

    a = 0.0;
    for (int i = tid; i < P1_BLOCKS; i += LT) a += (double)g_bnd_part[i];
    red[tid] = a; __syncthreads();
    for (int o = LT / 2; o; o >>= 1) { if (tid < o) red[tid] += red[tid + o]; __syncthreads(); }
    const double bnd_sum = red[0]; __syncthreads();

    // dice: per-image 2*sum(p*t) / (sum(p) + sum(t) + eps)
    a = 0.0;
    if (tid < BATCH) {
        double pt = 0.0, pp = 0.0; long long cnt = 0;
        for (int b = tid * NPART; b < (tid + 1) * NPART; b++) {
            pt  += (double)g_pt_part [b];
            pp  += (double)g_p_part  [b];
            cnt += (long long)g_cnt_part[b];
        }
        a = 2.0 * pt / (pp + (double)cnt + EPS_D);
    }
    red[tid] = a; __syncthreads();
    for (int o = LT / 2; o; o >>= 1) { if (tid < o) red[tid] += red[tid + o]; __syncthreads(); }
    const double dice_sum = red[0]; __syncthreads();

    a = (tid < BATCH) ? (double)g_lov_img[tid] : 0.0;
    red[tid] = a; __syncthreads();
    for (int o = LT / 2; o; o >>= 1) { if (tid < o) red[tid] += red[tid + o]; __syncthreads(); }
    const double lov_sum = red[0];

    if (tid == 0) {
        const double invN = 1.0 / (double)NTOT;
        const double loss = ALPHA * (bce_sum * invN)
                          + BETA  * (1.0 - dice_sum / (double)BATCH)
                          + GAMMA * (bnd_sum * invN)
                          + DELTA * (lov_sum / (double)BATCH);
        out[0] = (float)loss;
        g_done = 0;                       // reset for next graph replay
    }
}

// ---------------------------------------------------------------------------
// Launch: 2 kernels, no global atomics in the hot path, no zeroing pass.
// ---------------------------------------------------------------------------
extern "C" void kernel_launch(void* const* d_in, const int* in_sizes, int n_in,
                              void* d_out, int out_size)
{
    const float* logits  = (const float*)d_in[0];
    const float* targets = (const float*)d_in[1];

    pass1_kernel<<<P1_BLOCKS, P1_TPB>>>(logits, targets);
    lov_kernel  <<<BATCH, LT>>>((float*)d_out);
}